// round 1
// baseline (speedup 1.0000x reference)
#include <cuda_runtime.h>
#include <cuda_bf16.h>

// Problem constants
#define BATCH 64
#define SEQ   256
#define INP   1024
#define HID   1024
#define NG    4096            // 4*HID gate columns (i,f,g,o)
#define MTOT  (BATCH*SEQ)     // 16384 rows of the input projection

// -------- device scratch (static globals: no allocation allowed) ----------
__device__ float g_gin[(size_t)MTOT * NG];   // 256 MB: X @ Wi^T + b_i + b_h
__device__ float g_part[8 * BATCH * NG];     // 8 MB: K-split partials of h @ Wh^T
__device__ float g_h[BATCH * HID];
__device__ float g_c[BATCH * HID];
__device__ unsigned g_bar_count = 0;
__device__ unsigned g_bar_gen   = 0;

// -------- packed f32x2 helpers (doubles fp32 FMA throughput on sm_103a) ---
__device__ __forceinline__ unsigned long long pack2(float x) {
    unsigned long long r;
    unsigned xi = __float_as_uint(x);
    asm("mov.b64 %0, {%1, %1};" : "=l"(r) : "r"(xi));
    return r;
}
__device__ __forceinline__ void fma2(unsigned long long& d,
                                     unsigned long long a,
                                     unsigned long long b) {
    asm("fma.rn.f32x2 %0, %1, %2, %0;" : "+l"(d) : "l"(a), "l"(b));
}
__device__ __forceinline__ float2 unpack2(unsigned long long v) {
    unsigned lo, hi;
    asm("mov.b64 {%0, %1}, %2;" : "=r"(lo), "=r"(hi) : "l"(v));
    float2 f;
    f.x = __uint_as_float(lo);
    f.y = __uint_as_float(hi);
    return f;
}

// ---------------------------------------------------------------------------
// Kernel 0: copy initial state into device scratch
// ---------------------------------------------------------------------------
__global__ void init_state(const float* __restrict__ h0, const float* __restrict__ c0) {
    int i = blockIdx.x * blockDim.x + threadIdx.x;
    if (i < BATCH * HID) {
        g_h[i] = h0[i];
        g_c[i] = c0[i];
    }
}

// ---------------------------------------------------------------------------
// Kernel 1: Gin = X @ Wi^T + (b_i + b_h)
// M=16384, N=4096, K=1024. 128x128x16 tiles, 256 threads, 8x8 per thread,
// accumulators packed as f32x2 pairs along N.
// ---------------------------------------------------------------------------
__global__ __launch_bounds__(256) void gemm_input(const float* __restrict__ X,
                                                  const float* __restrict__ Wi,
                                                  const float* __restrict__ bi,
                                                  const float* __restrict__ bh) {
    __shared__ float As[16][130];   // [k][m], pad keeps STS banks distinct, 8B aligned rows
    __shared__ float Bs[16][130];   // [k][n]

    const int tid   = threadIdx.x;
    const int mbase = blockIdx.y * 128;
    const int nbase = blockIdx.x * 128;
    const int ty    = tid >> 4;     // 0..15 -> rows ty*8..ty*8+7
    const int tx    = tid & 15;     // 0..15 -> cols tx*8..tx*8+7

    unsigned long long acc[8][4];
#pragma unroll
    for (int i = 0; i < 8; i++)
#pragma unroll
        for (int j = 0; j < 4; j++) acc[i][j] = 0ull;

    for (int k0 = 0; k0 < INP; k0 += 16) {
#pragma unroll
        for (int it = 0; it < 2; it++) {
            int idx = tid + it * 256;            // 0..511
            int row = idx >> 2;                  // 0..127
            int kq  = (idx & 3) << 2;            // 0,4,8,12
            float4 va = *(const float4*)(X  + (size_t)(mbase + row) * INP + k0 + kq);
            As[kq + 0][row] = va.x; As[kq + 1][row] = va.y;
            As[kq + 2][row] = va.z; As[kq + 3][row] = va.w;
            float4 vb = *(const float4*)(Wi + (size_t)(nbase + row) * INP + k0 + kq);
            Bs[kq + 0][row] = vb.x; Bs[kq + 1][row] = vb.y;
            Bs[kq + 2][row] = vb.z; Bs[kq + 3][row] = vb.w;
        }
        __syncthreads();

#pragma unroll
        for (int kk = 0; kk < 16; kk++) {
            float a[8];
#pragma unroll
            for (int i = 0; i < 8; i++) a[i] = As[kk][ty * 8 + i];
            unsigned long long b2[4];
            const unsigned long long* bp =
                reinterpret_cast<const unsigned long long*>(&Bs[kk][tx * 8]);
#pragma unroll
            for (int j = 0; j < 4; j++) b2[j] = bp[j];
#pragma unroll
            for (int i = 0; i < 8; i++) {
                unsigned long long a2 = pack2(a[i]);
#pragma unroll
                for (int j = 0; j < 4; j++) fma2(acc[i][j], a2, b2[j]);
            }
        }
        __syncthreads();
    }

#pragma unroll
    for (int i = 0; i < 8; i++) {
        size_t m = (size_t)(mbase + ty * 8 + i);
#pragma unroll
        for (int j = 0; j < 4; j++) {
            int n = nbase + tx * 8 + j * 2;
            float2 v = unpack2(acc[i][j]);
            g_gin[m * NG + n + 0] = v.x + bi[n + 0] + bh[n + 0];
            g_gin[m * NG + n + 1] = v.y + bi[n + 1] + bh[n + 1];
        }
    }
}

// ---------------------------------------------------------------------------
// Grid-wide barrier (sense-reversing, generation counter survives graph replays)
// ---------------------------------------------------------------------------
__device__ __forceinline__ void grid_barrier() {
    __syncthreads();
    if (threadIdx.x == 0) {
        __threadfence();
        unsigned gen = atomicAdd(&g_bar_gen, 0u);
        unsigned t   = atomicAdd(&g_bar_count, 1u);
        if (t == gridDim.x - 1) {
            atomicExch(&g_bar_count, 0u);
            __threadfence();
            atomicAdd(&g_bar_gen, 1u);
        } else {
            while (atomicAdd(&g_bar_gen, 0u) == gen) __nanosleep(32);
        }
        __threadfence();
    }
    __syncthreads();
}

__device__ __forceinline__ float sigmoidf_(float x) {
    return 1.0f / (1.0f + expf(-x));
}

// ---------------------------------------------------------------------------
// Kernel 2: persistent recurrence. 128 CTAs x 256 threads.
// CTA c: cn = c%16 owns gate cols [cn*256, cn*256+256), ck = c/16 owns
// K slice [ck*128, ck*128+128). Per step:
//   phase 1: partial GEMM h @ Wh^T into g_part[ck]  -> barrier
//   phase 2: reduce partials + Gin, gate math, update h/c, write outputs -> barrier
// ---------------------------------------------------------------------------
__global__ __launch_bounds__(256, 1) void lstm_recurrent(const float* __restrict__ Wh,
                                                         float* __restrict__ hidden,
                                                         float* __restrict__ hfin,
                                                         float* __restrict__ cfin) {
    __shared__ float Hs[16][66];    // [k][m]  (64 rows)
    __shared__ float Ws[16][258];   // [k][n]  (256 gate cols)

    const int tid   = threadIdx.x;
    const int c     = blockIdx.x;
    const int cn    = c & 15;
    const int ck    = c >> 4;
    const int nbase = cn * 256;
    const int kbase = ck * 128;
    const int rg    = (tid >> 5) * 8;   // row group 0..56
    const int c0    = (tid & 31) * 8;   // col within tile 0..248

    for (int t = 0; t < SEQ; t++) {
        // ---------------- phase 1: partial GEMM ----------------
        unsigned long long acc[8][4];
#pragma unroll
        for (int i = 0; i < 8; i++)
#pragma unroll
            for (int j = 0; j < 4; j++) acc[i][j] = 0ull;

        for (int kt = 0; kt < 8; kt++) {
            const int kk0 = kbase + kt * 16;
            {   // load h tile 64x16
                int row = tid >> 2;
                int kq  = (tid & 3) << 2;
                float4 v = *(const float4*)(&g_h[row * HID + kk0 + kq]);
                Hs[kq + 0][row] = v.x; Hs[kq + 1][row] = v.y;
                Hs[kq + 2][row] = v.z; Hs[kq + 3][row] = v.w;
            }
            {   // load Wh tile 256x16 (rows = gate cols nbase..nbase+255)
#pragma unroll
                for (int q = 0; q < 4; q++) {
                    float4 v = *(const float4*)(Wh + (size_t)(nbase + tid) * HID + kk0 + q * 4);
                    Ws[q * 4 + 0][tid] = v.x; Ws[q * 4 + 1][tid] = v.y;
                    Ws[q * 4 + 2][tid] = v.z; Ws[q * 4 + 3][tid] = v.w;
                }
            }
            __syncthreads();

#pragma unroll
            for (int kk = 0; kk < 16; kk++) {
                float a[8];
#pragma unroll
                for (int i = 0; i < 8; i++) a[i] = Hs[kk][rg + i];
                unsigned long long b2[4];
                const unsigned long long* bp =
                    reinterpret_cast<const unsigned long long*>(&Ws[kk][c0]);
#pragma unroll
                for (int j = 0; j < 4; j++) b2[j] = bp[j];
#pragma unroll
                for (int i = 0; i < 8; i++) {
                    unsigned long long a2 = pack2(a[i]);
#pragma unroll
                    for (int j = 0; j < 4; j++) fma2(acc[i][j], a2, b2[j]);
                }
            }
            __syncthreads();
        }

        // store partials: g_part[ck][row][col]
#pragma unroll
        for (int i = 0; i < 8; i++) {
            int row = rg + i;
            float* dst = &g_part[(size_t)(ck * 64 + row) * NG + nbase + c0];
#pragma unroll
            for (int j = 0; j < 4; j++) {
                float2 v = unpack2(acc[i][j]);
                *reinterpret_cast<float2*>(dst + 2 * j) = v;
            }
        }

        grid_barrier();

        // ---------------- phase 2: gates + state update ----------------
#pragma unroll
        for (int p = 0; p < 2; p++) {
            int e  = c * 256 + tid + p * 32768;  // 0..65535
            int b  = e >> 10;
            int hh = e & 1023;
            size_t grow = ((size_t)b * SEQ + t) * NG;

            float pre[4];
#pragma unroll
            for (int q = 0; q < 4; q++) {
                float s = __ldg(&g_gin[grow + q * HID + hh]);
#pragma unroll
                for (int ks = 0; ks < 8; ks++)
                    s += g_part[(size_t)(ks * 64 + b) * NG + q * HID + hh];
                pre[q] = s;
            }
            float ig = sigmoidf_(pre[0]);
            float fg = sigmoidf_(pre[1]);
            float gg = tanhf(pre[2]);
            float og = sigmoidf_(pre[3]);

            float cnew = fg * g_c[e] + ig * gg;
            float hnew = og * tanhf(cnew);
            g_c[e] = cnew;
            g_h[e] = hnew;
            hidden[((size_t)b * SEQ + t) * HID + hh] = hnew;
            if (t == SEQ - 1) {
                hfin[e] = hnew;
                cfin[e] = cnew;
            }
        }

        grid_barrier();
    }
}

// ---------------------------------------------------------------------------
// kernel_launch
// inputs (metadata order): inputs, h0, c0, w_i, w_h, b_i, b_h
// output: [hidden_seq (B,S,H) | h_final (B,H) | c_final (B,H)]
// ---------------------------------------------------------------------------
extern "C" void kernel_launch(void* const* d_in, const int* in_sizes, int n_in,
                              void* d_out, int out_size) {
    const float* X   = (const float*)d_in[0];
    const float* h0  = (const float*)d_in[1];
    const float* c0  = (const float*)d_in[2];
    const float* Wi  = (const float*)d_in[3];
    const float* Wh  = (const float*)d_in[4];
    const float* bi  = (const float*)d_in[5];
    const float* bh  = (const float*)d_in[6];

    float* out    = (float*)d_out;
    float* hidden = out;                                   // B*S*H
    float* hfin   = out + (size_t)BATCH * SEQ * HID;       // B*H
    float* cfin   = hfin + (size_t)BATCH * HID;            // B*H

    init_state<<<256, 256>>>(h0, c0);
    gemm_input<<<dim3(NG / 128, MTOT / 128), 256>>>(X, Wi, bi, bh);
    lstm_recurrent<<<128, 256>>>(Wh, hidden, hfin, cfin);
}

// round 2
// speedup vs baseline: 1.0024x; 1.0024x over previous
#include <cuda_runtime.h>
#include <cuda_bf16.h>

// Problem constants
#define BATCH 64
#define SEQ   256
#define INP   1024
#define HID   1024
#define NG    4096            // 4*HID gate columns (i,f,g,o)
#define MTOT  (BATCH*SEQ)     // 16384 rows of the input projection

// -------- device scratch (static globals: no allocation allowed) ----------
__device__ float g_gin[(size_t)MTOT * NG];   // 256 MB: X @ Wi^T + b_i + b_h
__device__ float g_part[8 * BATCH * NG];     // 8 MB: K-split partials of h @ Wh^T
__device__ float g_h[BATCH * HID];
__device__ float g_c[BATCH * HID];
__device__ unsigned g_bar_count = 0;
__device__ unsigned g_bar_gen   = 0;

// -------- packed f32x2 helpers (doubles fp32 FMA throughput on sm_103a) ---
__device__ __forceinline__ unsigned long long pack2(float x) {
    unsigned long long r;
    unsigned xi = __float_as_uint(x);
    asm("mov.b64 %0, {%1, %1};" : "=l"(r) : "r"(xi));
    return r;
}
__device__ __forceinline__ void fma2(unsigned long long& d,
                                     unsigned long long a,
                                     unsigned long long b) {
    asm("fma.rn.f32x2 %0, %1, %2, %0;" : "+l"(d) : "l"(a), "l"(b));
}
__device__ __forceinline__ float2 unpack2(unsigned long long v) {
    unsigned lo, hi;
    asm("mov.b64 {%0, %1}, %2;" : "=r"(lo), "=r"(hi) : "l"(v));
    float2 f;
    f.x = __uint_as_float(lo);
    f.y = __uint_as_float(hi);
    return f;
}

// ---------------------------------------------------------------------------
// Kernel 0: copy initial state into device scratch
// ---------------------------------------------------------------------------
__global__ void init_state(const float* __restrict__ h0, const float* __restrict__ c0) {
    int i = blockIdx.x * blockDim.x + threadIdx.x;
    if (i < BATCH * HID) {
        g_h[i] = h0[i];
        g_c[i] = c0[i];
    }
}

// ---------------------------------------------------------------------------
// Kernel 1: Gin = X @ Wi^T + (b_i + b_h)
// M=16384, N=4096, K=1024. 128x128x16 tiles, 256 threads, 8x8 per thread,
// accumulators packed as f32x2 pairs along N.
// ---------------------------------------------------------------------------
__global__ __launch_bounds__(256) void gemm_input(const float* __restrict__ X,
                                                  const float* __restrict__ Wi,
                                                  const float* __restrict__ bi,
                                                  const float* __restrict__ bh) {
    __shared__ float As[16][130];   // [k][m], pad keeps STS banks distinct, 8B aligned rows
    __shared__ float Bs[16][130];   // [k][n]

    const int tid   = threadIdx.x;
    const int mbase = blockIdx.y * 128;
    const int nbase = blockIdx.x * 128;
    const int ty    = tid >> 4;     // 0..15 -> rows ty*8..ty*8+7
    const int tx    = tid & 15;     // 0..15 -> cols tx*8..tx*8+7

    unsigned long long acc[8][4];
#pragma unroll
    for (int i = 0; i < 8; i++)
#pragma unroll
        for (int j = 0; j < 4; j++) acc[i][j] = 0ull;

    for (int k0 = 0; k0 < INP; k0 += 16) {
#pragma unroll
        for (int it = 0; it < 2; it++) {
            int idx = tid + it * 256;            // 0..511
            int row = idx >> 2;                  // 0..127
            int kq  = (idx & 3) << 2;            // 0,4,8,12
            float4 va = *(const float4*)(X  + (size_t)(mbase + row) * INP + k0 + kq);
            As[kq + 0][row] = va.x; As[kq + 1][row] = va.y;
            As[kq + 2][row] = va.z; As[kq + 3][row] = va.w;
            float4 vb = *(const float4*)(Wi + (size_t)(nbase + row) * INP + k0 + kq);
            Bs[kq + 0][row] = vb.x; Bs[kq + 1][row] = vb.y;
            Bs[kq + 2][row] = vb.z; Bs[kq + 3][row] = vb.w;
        }
        __syncthreads();

#pragma unroll
        for (int kk = 0; kk < 16; kk++) {
            float a[8];
#pragma unroll
            for (int i = 0; i < 8; i++) a[i] = As[kk][ty * 8 + i];
            unsigned long long b2[4];
            const unsigned long long* bp =
                reinterpret_cast<const unsigned long long*>(&Bs[kk][tx * 8]);
#pragma unroll
            for (int j = 0; j < 4; j++) b2[j] = bp[j];
#pragma unroll
            for (int i = 0; i < 8; i++) {
                unsigned long long a2 = pack2(a[i]);
#pragma unroll
                for (int j = 0; j < 4; j++) fma2(acc[i][j], a2, b2[j]);
            }
        }
        __syncthreads();
    }

#pragma unroll
    for (int i = 0; i < 8; i++) {
        size_t m = (size_t)(mbase + ty * 8 + i);
#pragma unroll
        for (int j = 0; j < 4; j++) {
            int n = nbase + tx * 8 + j * 2;
            float2 v = unpack2(acc[i][j]);
            g_gin[m * NG + n + 0] = v.x + bi[n + 0] + bh[n + 0];
            g_gin[m * NG + n + 1] = v.y + bi[n + 1] + bh[n + 1];
        }
    }
}

// ---------------------------------------------------------------------------
// Grid-wide barrier (sense-reversing, generation counter survives graph replays)
// ---------------------------------------------------------------------------
__device__ __forceinline__ void grid_barrier() {
    __syncthreads();
    if (threadIdx.x == 0) {
        __threadfence();
        unsigned gen = atomicAdd(&g_bar_gen, 0u);
        unsigned t   = atomicAdd(&g_bar_count, 1u);
        if (t == gridDim.x - 1) {
            atomicExch(&g_bar_count, 0u);
            __threadfence();
            atomicAdd(&g_bar_gen, 1u);
        } else {
            while (atomicAdd(&g_bar_gen, 0u) == gen) __nanosleep(32);
        }
        __threadfence();
    }
    __syncthreads();
}

__device__ __forceinline__ float sigmoidf_(float x) {
    return 1.0f / (1.0f + expf(-x));
}

// ---------------------------------------------------------------------------
// Kernel 2: persistent recurrence. 128 CTAs x 256 threads.
// CTA c: cn = c%16 owns gate cols [cn*256, cn*256+256), ck = c/16 owns
// K slice [ck*128, ck*128+128). Per step:
//   phase 1: partial GEMM h @ Wh^T into g_part[ck]  -> barrier
//   phase 2: reduce partials + Gin, gate math, update h/c, write outputs -> barrier
// ---------------------------------------------------------------------------
__global__ __launch_bounds__(256, 1) void lstm_recurrent(const float* __restrict__ Wh,
                                                         float* __restrict__ hidden,
                                                         float* __restrict__ hfin,
                                                         float* __restrict__ cfin) {
    __shared__ float Hs[16][66];    // [k][m]  (64 rows)
    __shared__ float Ws[16][258];   // [k][n]  (256 gate cols)

    const int tid   = threadIdx.x;
    const int c     = blockIdx.x;
    const int cn    = c & 15;
    const int ck    = c >> 4;
    const int nbase = cn * 256;
    const int kbase = ck * 128;
    const int rg    = (tid >> 5) * 8;   // row group 0..56
    const int c0    = (tid & 31) * 8;   // col within tile 0..248

    for (int t = 0; t < SEQ; t++) {
        // ---------------- phase 1: partial GEMM ----------------
        unsigned long long acc[8][4];
#pragma unroll
        for (int i = 0; i < 8; i++)
#pragma unroll
            for (int j = 0; j < 4; j++) acc[i][j] = 0ull;

        for (int kt = 0; kt < 8; kt++) {
            const int kk0 = kbase + kt * 16;
            {   // load h tile 64x16
                int row = tid >> 2;
                int kq  = (tid & 3) << 2;
                float4 v = *(const float4*)(&g_h[row * HID + kk0 + kq]);
                Hs[kq + 0][row] = v.x; Hs[kq + 1][row] = v.y;
                Hs[kq + 2][row] = v.z; Hs[kq + 3][row] = v.w;
            }
            {   // load Wh tile 256x16 (rows = gate cols nbase..nbase+255)
#pragma unroll
                for (int q = 0; q < 4; q++) {
                    float4 v = *(const float4*)(Wh + (size_t)(nbase + tid) * HID + kk0 + q * 4);
                    Ws[q * 4 + 0][tid] = v.x; Ws[q * 4 + 1][tid] = v.y;
                    Ws[q * 4 + 2][tid] = v.z; Ws[q * 4 + 3][tid] = v.w;
                }
            }
            __syncthreads();

#pragma unroll
            for (int kk = 0; kk < 16; kk++) {
                float a[8];
#pragma unroll
                for (int i = 0; i < 8; i++) a[i] = Hs[kk][rg + i];
                unsigned long long b2[4];
                const unsigned long long* bp =
                    reinterpret_cast<const unsigned long long*>(&Ws[kk][c0]);
#pragma unroll
                for (int j = 0; j < 4; j++) b2[j] = bp[j];
#pragma unroll
                for (int i = 0; i < 8; i++) {
                    unsigned long long a2 = pack2(a[i]);
#pragma unroll
                    for (int j = 0; j < 4; j++) fma2(acc[i][j], a2, b2[j]);
                }
            }
            __syncthreads();
        }

        // store partials: g_part[ck][row][col]
#pragma unroll
        for (int i = 0; i < 8; i++) {
            int row = rg + i;
            float* dst = &g_part[(size_t)(ck * 64 + row) * NG + nbase + c0];
#pragma unroll
            for (int j = 0; j < 4; j++) {
                float2 v = unpack2(acc[i][j]);
                *reinterpret_cast<float2*>(dst + 2 * j) = v;
            }
        }

        grid_barrier();

        // ---------------- phase 2: gates + state update ----------------
#pragma unroll
        for (int p = 0; p < 2; p++) {
            int e  = c * 256 + tid + p * 32768;  // 0..65535
            int b  = e >> 10;
            int hh = e & 1023;
            size_t grow = ((size_t)b * SEQ + t) * NG;

            float pre[4];
#pragma unroll
            for (int q = 0; q < 4; q++) {
                float s = __ldg(&g_gin[grow + q * HID + hh]);
#pragma unroll
                for (int ks = 0; ks < 8; ks++)
                    s += g_part[(size_t)(ks * 64 + b) * NG + q * HID + hh];
                pre[q] = s;
            }
            float ig = sigmoidf_(pre[0]);
            float fg = sigmoidf_(pre[1]);
            float gg = tanhf(pre[2]);
            float og = sigmoidf_(pre[3]);

            float cnew = fg * g_c[e] + ig * gg;
            float hnew = og * tanhf(cnew);
            g_c[e] = cnew;
            g_h[e] = hnew;
            hidden[((size_t)b * SEQ + t) * HID + hh] = hnew;
            if (t == SEQ - 1) {
                hfin[e] = hnew;
                cfin[e] = cnew;
            }
        }

        grid_barrier();
    }
}

// ---------------------------------------------------------------------------
// kernel_launch
// inputs (metadata order): inputs, h0, c0, w_i, w_h, b_i, b_h
// output: [hidden_seq (B,S,H) | h_final (B,H) | c_final (B,H)]
// ---------------------------------------------------------------------------
extern "C" void kernel_launch(void* const* d_in, const int* in_sizes, int n_in,
                              void* d_out, int out_size) {
    const float* X   = (const float*)d_in[0];
    const float* h0  = (const float*)d_in[1];
    const float* c0  = (const float*)d_in[2];
    const float* Wi  = (const float*)d_in[3];
    const float* Wh  = (const float*)d_in[4];
    const float* bi  = (const float*)d_in[5];
    const float* bh  = (const float*)d_in[6];

    float* out    = (float*)d_out;
    float* hidden = out;                                   // B*S*H
    float* hfin   = out + (size_t)BATCH * SEQ * HID;       // B*H
    float* cfin   = hfin + (size_t)BATCH * HID;            // B*H

    init_state<<<256, 256>>>(h0, c0);
    gemm_input<<<dim3(NG / 128, MTOT / 128), 256>>>(X, Wi, bi, bh);
    lstm_recurrent<<<128, 256>>>(Wh, hidden, hfin, cfin);
}

// round 3
// speedup vs baseline: 1.1565x; 1.1537x over previous
#include <cuda_runtime.h>
#include <cuda_bf16.h>

#define BATCH 64
#define SEQ   256
#define INP   1024
#define HID   1024
#define NG    4096
#define MTOT  (BATCH*SEQ)

// -------- device scratch ----------
__device__ float g_gin[(size_t)MTOT * NG];   // 256 MB: X @ Wi^T + b_i + b_h
__device__ float g_hbuf[2][BATCH * HID];     // double-buffered hidden state
__device__ float g_c[BATCH * HID];
__device__ unsigned g_bar_count = 0;
__device__ unsigned g_bar_gen   = 0;

// -------- packed f32x2 helpers ----------
__device__ __forceinline__ unsigned long long pack2(float x) {
    unsigned long long r;
    unsigned xi = __float_as_uint(x);
    asm("mov.b64 %0, {%1, %1};" : "=l"(r) : "r"(xi));
    return r;
}
__device__ __forceinline__ void fma2(unsigned long long& d,
                                     unsigned long long a,
                                     unsigned long long b) {
    asm("fma.rn.f32x2 %0, %1, %2, %0;" : "+l"(d) : "l"(a), "l"(b));
}
__device__ __forceinline__ float2 unpack2(unsigned long long v) {
    unsigned lo, hi;
    asm("mov.b64 {%0, %1}, %2;" : "=r"(lo), "=r"(hi) : "l"(v));
    float2 f;
    f.x = __uint_as_float(lo);
    f.y = __uint_as_float(hi);
    return f;
}

// ---------------------------------------------------------------------------
// Kernel 0: init state
// ---------------------------------------------------------------------------
__global__ void init_state(const float* __restrict__ h0, const float* __restrict__ c0) {
    int i = blockIdx.x * blockDim.x + threadIdx.x;
    if (i < BATCH * HID) {
        g_hbuf[0][i] = h0[i];
        g_c[i] = c0[i];
    }
}

// ---------------------------------------------------------------------------
// Kernel 1: Gin = X @ Wi^T + (b_i + b_h)
// M=16384, N=4096, K=1024. 128x128 tiles, KT=8, double-buffered smem with
// register prefetch (single __syncthreads per chunk). Per-thread 8x8 tile,
// accumulators packed as f32x2 along M (a-operand naturally packed).
// ---------------------------------------------------------------------------
#define GKT 8
__global__ __launch_bounds__(256) void gemm_input(const float* __restrict__ X,
                                                  const float* __restrict__ Wi,
                                                  const float* __restrict__ bi,
                                                  const float* __restrict__ bh) {
    __shared__ float As[2][GKT][132];   // [buf][k][m], 132*4=528=33*16 -> LDS.128 aligned
    __shared__ float Bs[2][GKT][132];   // [buf][k][n]

    const int tid   = threadIdx.x;
    const int mbase = blockIdx.y * 128;
    const int nbase = blockIdx.x * 128;
    const int ty    = tid >> 4;     // rows ty*8..ty*8+7
    const int tx    = tid & 15;     // cols tx*8..tx*8+7
    const int r0    = ty * 8;
    const int lrow  = tid >> 1;           // loader: row 0..127
    const int lkq   = (tid & 1) * 4;      // loader: k offset 0 or 4

    const float* Xrow  = X  + (size_t)(mbase + lrow) * INP + lkq;
    const float* Wirow = Wi + (size_t)(nbase + lrow) * INP + lkq;

    unsigned long long acc[4][8];   // [m-pair][col], m-pair p covers rows r0+2p, r0+2p+1
#pragma unroll
    for (int i = 0; i < 4; i++)
#pragma unroll
        for (int j = 0; j < 8; j++) acc[i][j] = 0ull;

    // prologue: load chunk 0
    {
        float4 va = *(const float4*)(Xrow);
        float4 vb = *(const float4*)(Wirow);
        As[0][lkq + 0][lrow] = va.x; As[0][lkq + 1][lrow] = va.y;
        As[0][lkq + 2][lrow] = va.z; As[0][lkq + 3][lrow] = va.w;
        Bs[0][lkq + 0][lrow] = vb.x; Bs[0][lkq + 1][lrow] = vb.y;
        Bs[0][lkq + 2][lrow] = vb.z; Bs[0][lkq + 3][lrow] = vb.w;
    }
    __syncthreads();

    const int NCHUNK = INP / GKT;   // 128
    for (int ck = 0; ck < NCHUNK; ck++) {
        const int cur = ck & 1;
        const int nxt = cur ^ 1;
        const bool pre = (ck + 1) < NCHUNK;
        float4 va, vb;
        if (pre) {
            int kn = (ck + 1) * GKT;
            va = *(const float4*)(Xrow  + kn);
            vb = *(const float4*)(Wirow + kn);
        }
#pragma unroll
        for (int kk = 0; kk < GKT; kk++) {
            ulonglong2 a01 = *(const ulonglong2*)&As[cur][kk][r0];
            ulonglong2 a23 = *(const ulonglong2*)&As[cur][kk][r0 + 4];
            float4 b03 = *(const float4*)&Bs[cur][kk][tx * 8];
            float4 b47 = *(const float4*)&Bs[cur][kk][tx * 8 + 4];
            unsigned long long b2[8];
            b2[0] = pack2(b03.x); b2[1] = pack2(b03.y);
            b2[2] = pack2(b03.z); b2[3] = pack2(b03.w);
            b2[4] = pack2(b47.x); b2[5] = pack2(b47.y);
            b2[6] = pack2(b47.z); b2[7] = pack2(b47.w);
#pragma unroll
            for (int j = 0; j < 8; j++) {
                fma2(acc[0][j], a01.x, b2[j]);
                fma2(acc[1][j], a01.y, b2[j]);
                fma2(acc[2][j], a23.x, b2[j]);
                fma2(acc[3][j], a23.y, b2[j]);
            }
        }
        if (pre) {
            As[nxt][lkq + 0][lrow] = va.x; As[nxt][lkq + 1][lrow] = va.y;
            As[nxt][lkq + 2][lrow] = va.z; As[nxt][lkq + 3][lrow] = va.w;
            Bs[nxt][lkq + 0][lrow] = vb.x; Bs[nxt][lkq + 1][lrow] = vb.y;
            Bs[nxt][lkq + 2][lrow] = vb.z; Bs[nxt][lkq + 3][lrow] = vb.w;
        }
        __syncthreads();
    }

    // epilogue: bias + store
    float bias[8];
#pragma unroll
    for (int j = 0; j < 8; j++) {
        int n = nbase + tx * 8 + j;
        bias[j] = bi[n] + bh[n];
    }
#pragma unroll
    for (int p = 0; p < 4; p++) {
        float lo[8], hi[8];
#pragma unroll
        for (int j = 0; j < 8; j++) {
            float2 v = unpack2(acc[p][j]);
            lo[j] = v.x + bias[j];
            hi[j] = v.y + bias[j];
        }
        size_t mA = (size_t)(mbase + r0 + 2 * p);
        float* dA = &g_gin[mA * NG + nbase + tx * 8];
        float* dB = dA + NG;
        *(float4*)(dA)     = make_float4(lo[0], lo[1], lo[2], lo[3]);
        *(float4*)(dA + 4) = make_float4(lo[4], lo[5], lo[6], lo[7]);
        *(float4*)(dB)     = make_float4(hi[0], hi[1], hi[2], hi[3]);
        *(float4*)(dB + 4) = make_float4(hi[4], hi[5], hi[6], hi[7]);
    }
}

// ---------------------------------------------------------------------------
// Grid-wide barrier (release: per-thread fence; acquire: atomic poll)
// ---------------------------------------------------------------------------
__device__ __forceinline__ void grid_barrier() {
    __threadfence();
    __syncthreads();
    if (threadIdx.x == 0) {
        unsigned gen = atomicAdd(&g_bar_gen, 0u);
        unsigned t   = atomicAdd(&g_bar_count, 1u);
        if (t == gridDim.x - 1) {
            atomicExch(&g_bar_count, 0u);
            atomicAdd(&g_bar_gen, 1u);
        } else {
            while (atomicAdd(&g_bar_gen, 0u) == gen) __nanosleep(64);
        }
    }
    __syncthreads();
}

__device__ __forceinline__ float sigmoidf_(float x) {
    return 1.0f / (1.0f + expf(-x));
}

// ---------------------------------------------------------------------------
// Kernel 2: persistent recurrence. 128 CTAs x 256 threads.
// CTA c owns hidden units [c*8, c*8+8) -> 32 gate columns (8 per gate), full K.
// Per step: GEMM h @ Wh^T for those columns (M=64,N=32,K=1024, f32x2 packed
// along M), add Gin, gate math locally, write h into the next h buffer,
// ONE grid barrier. No cross-CTA partials.
// ---------------------------------------------------------------------------
#define RKT 32
__global__ __launch_bounds__(256, 1) void lstm_recurrent(const float* __restrict__ Wh,
                                                         float* __restrict__ hidden,
                                                         float* __restrict__ hfin,
                                                         float* __restrict__ cfin) {
    __shared__ float Hs[2][RKT][68];    // [buf][k][m 0..63], 68*4=272=17*16 aligned
    __shared__ float Ws[2][RKT][34];    // [buf][k][n 0..31], 34*4=136=17*8 aligned
    __shared__ float Pre[64][34];       // pre-activations [batch][n_local]

    const int tid = threadIdx.x;
    const int c   = blockIdx.x;
    const int u0  = c * 8;              // first hidden unit owned

    // compute mapping: 4 rows x 2 cols per thread
    const int rg = tid >> 4;            // 0..15
    const int r0 = rg * 4;              // rows r0..r0+3 (batch)
    const int cp = tid & 15;            // 0..15
    const int n0 = cp * 2;              // local cols n0, n0+1

    // loader mapping for Ws: n = tid>>3 (0..31), kq = (tid&7)*4
    const int wn  = tid >> 3;
    const int wkq = (tid & 7) * 4;
    const int wgcol = (wn >> 3) * HID + u0 + (wn & 7);
    const float* Wrow = Wh + (size_t)wgcol * HID + wkq;

    // loader mapping for Hs (x2): idx = tid + j*256; m = idx>>3, kq = (idx&7)*4
    const int hm0  = tid >> 3;          // 0..31
    const int hm1  = hm0 + 32;          // 32..63
    const int hkq  = (tid & 7) * 4;

    // gin columns for this thread
    const int gc = (n0 >> 3) * HID + u0 + (n0 & 7);     // n0,n0+1 adjacent

    const int NCHUNK = HID / RKT;       // 32

    for (int t = 0; t < SEQ; t++) {
        const float* hsrc = g_hbuf[t & 1];
        float*       hdst = g_hbuf[(t + 1) & 1];

        // ---- prologue: load chunk 0 ----
        {
            float4 h0v = __ldcg((const float4*)(hsrc + hm0 * HID + hkq));
            float4 h1v = __ldcg((const float4*)(hsrc + hm1 * HID + hkq));
            float4 wv  = *(const float4*)(Wrow);
            Hs[0][hkq + 0][hm0] = h0v.x; Hs[0][hkq + 1][hm0] = h0v.y;
            Hs[0][hkq + 2][hm0] = h0v.z; Hs[0][hkq + 3][hm0] = h0v.w;
            Hs[0][hkq + 0][hm1] = h1v.x; Hs[0][hkq + 1][hm1] = h1v.y;
            Hs[0][hkq + 2][hm1] = h1v.z; Hs[0][hkq + 3][hm1] = h1v.w;
            Ws[0][wkq + 0][wn] = wv.x; Ws[0][wkq + 1][wn] = wv.y;
            Ws[0][wkq + 2][wn] = wv.z; Ws[0][wkq + 3][wn] = wv.w;
        }
        __syncthreads();

        unsigned long long acc00 = 0ull, acc01 = 0ull, acc10 = 0ull, acc11 = 0ull;

        for (int ck = 0; ck < NCHUNK; ck++) {
            const int cur = ck & 1;
            const int nxt = cur ^ 1;
            const bool pre = (ck + 1) < NCHUNK;
            float4 ph0, ph1, pw;
            if (pre) {
                int kn = (ck + 1) * RKT;
                ph0 = __ldcg((const float4*)(hsrc + hm0 * HID + kn + hkq));
                ph1 = __ldcg((const float4*)(hsrc + hm1 * HID + kn + hkq));
                pw  = *(const float4*)(Wrow + kn);
            }
#pragma unroll
            for (int kk = 0; kk < RKT; kk++) {
                ulonglong2 ap = *(const ulonglong2*)&Hs[cur][kk][r0];
                float2 bv = *(const float2*)&Ws[cur][kk][n0];
                unsigned long long b0 = pack2(bv.x);
                unsigned long long b1 = pack2(bv.y);
                fma2(acc00, ap.x, b0);
                fma2(acc01, ap.x, b1);
                fma2(acc10, ap.y, b0);
                fma2(acc11, ap.y, b1);
            }
            if (pre) {
                Hs[nxt][hkq + 0][hm0] = ph0.x; Hs[nxt][hkq + 1][hm0] = ph0.y;
                Hs[nxt][hkq + 2][hm0] = ph0.z; Hs[nxt][hkq + 3][hm0] = ph0.w;
                Hs[nxt][hkq + 0][hm1] = ph1.x; Hs[nxt][hkq + 1][hm1] = ph1.y;
                Hs[nxt][hkq + 2][hm1] = ph1.z; Hs[nxt][hkq + 3][hm1] = ph1.w;
                Ws[nxt][wkq + 0][wn] = pw.x; Ws[nxt][wkq + 1][wn] = pw.y;
                Ws[nxt][wkq + 2][wn] = pw.z; Ws[nxt][wkq + 3][wn] = pw.w;
            }
            __syncthreads();
        }

        // ---- add Gin, stage pre-activations in smem ----
        {
            float2 a00 = unpack2(acc00);   // col n0,   rows r0, r0+1
            float2 a01 = unpack2(acc01);   // col n0+1, rows r0, r0+1
            float2 a10 = unpack2(acc10);   // col n0,   rows r0+2, r0+3
            float2 a11 = unpack2(acc11);
            size_t base = ((size_t)r0 * SEQ + t) * NG + gc;
            float2 g0 = *(const float2*)&g_gin[base];
            float2 g1 = *(const float2*)&g_gin[base + (size_t)SEQ * NG];
            float2 g2 = *(const float2*)&g_gin[base + 2 * (size_t)SEQ * NG];
            float2 g3 = *(const float2*)&g_gin[base + 3 * (size_t)SEQ * NG];
            Pre[r0 + 0][n0]     = a00.x + g0.x;
            Pre[r0 + 0][n0 + 1] = a01.x + g0.y;
            Pre[r0 + 1][n0]     = a00.y + g1.x;
            Pre[r0 + 1][n0 + 1] = a01.y + g1.y;
            Pre[r0 + 2][n0]     = a10.x + g2.x;
            Pre[r0 + 2][n0 + 1] = a11.x + g2.y;
            Pre[r0 + 3][n0]     = a10.y + g3.x;
            Pre[r0 + 3][n0 + 1] = a11.y + g3.y;
        }
        __syncthreads();

        // ---- gate math: 512 elements, 2 per thread ----
#pragma unroll
        for (int p = 0; p < 2; p++) {
            int e  = tid + p * 256;         // 0..511
            int b  = e >> 3;                // batch
            int ui = e & 7;                 // unit within CTA
            int u  = u0 + ui;
            int ce = b * HID + u;
            float pi = Pre[b][ui];
            float pf = Pre[b][8 + ui];
            float pg = Pre[b][16 + ui];
            float po = Pre[b][24 + ui];
            float ig = sigmoidf_(pi);
            float fg = sigmoidf_(pf);
            float gg = tanhf(pg);
            float og = sigmoidf_(po);
            float cnew = fg * g_c[ce] + ig * gg;
            float hnew = og * tanhf(cnew);
            g_c[ce]  = cnew;
            hdst[ce] = hnew;
            hidden[((size_t)b * SEQ + t) * HID + u] = hnew;
            if (t == SEQ - 1) {
                hfin[ce] = hnew;
                cfin[ce] = cnew;
            }
        }

        grid_barrier();
    }
}

// ---------------------------------------------------------------------------
// kernel_launch
// ---------------------------------------------------------------------------
extern "C" void kernel_launch(void* const* d_in, const int* in_sizes, int n_in,
                              void* d_out, int out_size) {
    const float* X   = (const float*)d_in[0];
    const float* h0  = (const float*)d_in[1];
    const float* c0  = (const float*)d_in[2];
    const float* Wi  = (const float*)d_in[3];
    const float* Wh  = (const float*)d_in[4];
    const float* bi  = (const float*)d_in[5];
    const float* bh  = (const float*)d_in[6];

    float* out    = (float*)d_out;
    float* hidden = out;
    float* hfin   = out + (size_t)BATCH * SEQ * HID;
    float* cfin   = hfin + (size_t)BATCH * HID;

    init_state<<<256, 256>>>(h0, c0);
    gemm_input<<<dim3(NG / 128, MTOT / 128), 256>>>(X, Wi, bi, bh);
    lstm_recurrent<<<128, 256>>>(Wh, hidden, hfin, cfin);
}